// round 7
// baseline (speedup 1.0000x reference)
#include <cuda_runtime.h>
#include <cuda_fp16.h>
#include <cstdint>

// ============================================================================
// SpikingMLP via fp16 split-product HMMA.
// GEMM: CTA tile 256m x 128n, 8 warps (4m x 2n), warp tile 64x64, BK=64,
//       3-stage cp.async ring, ldmatrix + mma.sync m16n8k16.
// Dedup remap: GEMM1 logical K=2304 = [xh|xm|xh]/[w1h|w1h|w1m] over phys 1536;
//              GEMM2 logical K=6144 = [s1|s1]/[w2h|w2m] over phys 3072/6144.
// ============================================================================

#define MT 25088      // T*B*N
#define MR 6272       // B*N
#define N1 3072
#define N2 768
#define KA1 1536
#define KB1 1536
#define KA2 3072
#define KB2 6144

__device__ __align__(128) __half g_A1[(size_t)MT * KA1];
__device__ __align__(128) __half g_W1[(size_t)N1 * KB1];
__device__ __align__(128) __half g_s1[(size_t)MT * KA2];
__device__ __align__(128) __half g_W2[(size_t)N2 * KB2];
__device__ __align__(128) float  g_h [(size_t)MT * N1];
__device__ __align__(128) float  g_y [(size_t)MT * N2];

// ---------------- helpers ----------------
__device__ __forceinline__ uint32_t smem_u32(const void* p) {
    uint32_t a;
    asm("{ .reg .u64 t; cvta.to.shared.u64 t, %1; cvt.u32.u64 %0, t; }" : "=r"(a) : "l"(p));
    return a;
}
__device__ __forceinline__ void cp_async16(uint32_t dst, const void* src) {
    asm volatile("cp.async.cg.shared.global [%0], [%1], 16;" :: "r"(dst), "l"(src) : "memory");
}
__device__ __forceinline__ void cp_commit() { asm volatile("cp.async.commit_group;" ::: "memory"); }
__device__ __forceinline__ void cp_wait1()  { asm volatile("cp.async.wait_group 1;" ::: "memory"); }
__device__ __forceinline__ void ldmx4(uint32_t* r, uint32_t addr) {
    asm volatile("ldmatrix.sync.aligned.m8n8.x4.shared.b16 {%0,%1,%2,%3}, [%4];"
                 : "=r"(r[0]), "=r"(r[1]), "=r"(r[2]), "=r"(r[3]) : "r"(addr));
}
__device__ __forceinline__ void mma16816(float* d, const uint32_t* a, uint32_t b0, uint32_t b1) {
    asm volatile(
        "mma.sync.aligned.m16n8k16.row.col.f32.f16.f16.f32 "
        "{%0,%1,%2,%3}, {%4,%5,%6,%7}, {%8,%9}, {%0,%1,%2,%3};"
        : "+f"(d[0]), "+f"(d[1]), "+f"(d[2]), "+f"(d[3])
        : "r"(a[0]), "r"(a[1]), "r"(a[2]), "r"(a[3]), "r"(b0), "r"(b1));
}
__device__ __forceinline__ uint32_t packh2(float a, float b) {
    __half2 h = __floats2half2_rn(a, b);
    return *(uint32_t*)&h;
}

// stage layout: A tile 256x64 fp16 = 32KB, B tile 128x64 fp16 = 16KB
#define STG_BYTES 49152u
#define B_OFF     32768u

// ---------------- GEMM: C[M,N] = A[M,Klog] @ B[N,Klog]^T, col remap ----------
template<int MODA, int MODB>
__global__ __launch_bounds__(256, 1)
void hgemm_kernel(const __half* __restrict__ A, const __half* __restrict__ B,
                  float* __restrict__ C, int K, int N, int KaPhys, int KbPhys)
{
    extern __shared__ __align__(128) char smem_raw[];
    const uint32_t sbase = smem_u32(smem_raw);

    const int tid  = threadIdx.x;
    const int wid  = tid >> 5;
    const int lane = tid & 31;
    const int m0   = blockIdx.y * 256;
    const int n0   = blockIdx.x * 128;

    const int wm0 = (wid >> 1) * 64;     // warp m offset (0,64,128,192)
    const int wn0 = (wid & 1) * 64;      // warp n offset (0,64)

    const int lr = tid >> 3;             // loader row base (+j*32)
    const int lc = tid & 7;              // 16B chunk

    float acc[4][8][4];
#pragma unroll
    for (int mi = 0; mi < 4; mi++)
#pragma unroll
        for (int j = 0; j < 8; j++)
#pragma unroll
            for (int r = 0; r < 4; r++) acc[mi][j][r] = 0.0f;

    const int S = K >> 6;

#define LOAD_STAGE(sidx)                                                            \
    do {                                                                            \
        const int k0_  = (sidx) << 6;                                               \
        const int ka0_ = (k0_ >= MODA) ? (k0_ - MODA) : k0_;                        \
        const int kb0_ = (k0_ >= MODB) ? (k0_ - MODB) : k0_;                        \
        const uint32_t Ad = sbase + (uint32_t)((sidx) % 3) * STG_BYTES;             \
        const uint32_t Bd = Ad + B_OFF;                                             \
        _Pragma("unroll")                                                           \
        for (int j = 0; j < 8; j++) {                                               \
            const int r_ = lr + j * 32;                                             \
            const uint32_t doff = (uint32_t)(r_ * 128 + ((lc ^ (r_ & 7)) << 4));    \
            cp_async16(Ad + doff,                                                   \
                       (const char*)(A + (size_t)(m0 + r_) * KaPhys + ka0_) + lc * 16); \
        }                                                                           \
        _Pragma("unroll")                                                           \
        for (int j = 0; j < 4; j++) {                                               \
            const int r_ = lr + j * 32;                                             \
            const uint32_t doff = (uint32_t)(r_ * 128 + ((lc ^ (r_ & 7)) << 4));    \
            cp_async16(Bd + doff,                                                   \
                       (const char*)(B + (size_t)(n0 + r_) * KbPhys + kb0_) + lc * 16); \
        }                                                                           \
    } while (0)

    LOAD_STAGE(0); cp_commit();
    LOAD_STAGE(1); cp_commit();

    // ldmatrix per-thread geometry
    const int g  = lane >> 3;            // 0..3
    const int r8 = lane & 7;
    int a_m[4]; uint32_t a_rowoff[4];
#pragma unroll
    for (int mi = 0; mi < 4; mi++) {
        a_m[mi] = wm0 + mi * 16 + (g & 1) * 8 + r8;
        a_rowoff[mi] = (uint32_t)(a_m[mi] * 128);
    }
    int b_n[4]; uint32_t b_rowoff[4];
#pragma unroll
    for (int p = 0; p < 4; p++) {
        b_n[p] = wn0 + p * 16 + (g >> 1) * 8 + r8;
        b_rowoff[p] = (uint32_t)(b_n[p] * 128);
    }

    for (int s = 0; s < S; s++) {
        cp_wait1();
        __syncthreads();
        if (s + 2 < S) LOAD_STAGE(s + 2);
        cp_commit();

        const uint32_t Ab = sbase + (uint32_t)((s % 3)) * STG_BYTES;
        const uint32_t Bb = Ab + B_OFF;

#pragma unroll
        for (int ki = 0; ki < 4; ki++) {
            uint32_t af[4][4];
#pragma unroll
            for (int mi = 0; mi < 4; mi++) {
                const int c = 2 * ki + (g >> 1);
                ldmx4(af[mi], Ab + a_rowoff[mi] + (uint32_t)(((c ^ (a_m[mi] & 7)) << 4)));
            }
            uint32_t bf[4][4];
#pragma unroll
            for (int p = 0; p < 4; p++) {
                const int c = 2 * ki + (g & 1);
                ldmx4(bf[p], Bb + b_rowoff[p] + (uint32_t)(((c ^ (b_n[p] & 7)) << 4)));
            }
#pragma unroll
            for (int mi = 0; mi < 4; mi++)
#pragma unroll
                for (int p = 0; p < 4; p++) {
                    mma16816(acc[mi][2 * p],     af[mi], bf[p][0], bf[p][1]);
                    mma16816(acc[mi][2 * p + 1], af[mi], bf[p][2], bf[p][3]);
                }
        }
    }

    // epilogue
#pragma unroll
    for (int mi = 0; mi < 4; mi++) {
        const int row = m0 + wm0 + mi * 16 + (lane >> 2);
#pragma unroll
        for (int j = 0; j < 8; j++) {
            const int col = n0 + wn0 + j * 8 + (lane & 3) * 2;
            float* p0 = C + (size_t)row * N + col;
            *(float2*)p0 = make_float2(acc[mi][j][0], acc[mi][j][1]);
            float* p1 = p0 + (size_t)8 * N;
            *(float2*)p1 = make_float2(acc[mi][j][2], acc[mi][j][3]);
        }
    }
#undef LOAD_STAGE
}

// ---------------- split kernels ----------------
__global__ void split_x_kernel(const float* __restrict__ x, __half* __restrict__ A1)
{
    int i = blockIdx.x * blockDim.x + threadIdx.x;
    if (i >= MT * 192) return;
    const int row = i / 192, col = (i % 192) * 4;
    float4 v = *(const float4*)(x + (size_t)row * 768 + col);
    float a[4] = {v.x, v.y, v.z, v.w};
    float hs[4], ms[4];
#pragma unroll
    for (int k = 0; k < 4; k++) {
        __half h = __float2half_rn(a[k]);
        hs[k] = __half2float(h);
        ms[k] = a[k] - hs[k];
    }
    uint2 ph = make_uint2(packh2(hs[0], hs[1]), packh2(hs[2], hs[3]));
    uint2 pm = make_uint2(packh2(ms[0], ms[1]), packh2(ms[2], ms[3]));
    __half* d = A1 + (size_t)row * KA1 + col;
    *(uint2*)d         = ph;
    *(uint2*)(d + 768) = pm;
}

__global__ void split_w1_kernel(const float* __restrict__ w, __half* __restrict__ W1p)
{
    int i = blockIdx.x * blockDim.x + threadIdx.x;
    if (i >= N1 * 192) return;
    const int row = i / 192, col = (i % 192) * 4;
    float4 v = *(const float4*)(w + (size_t)row * 768 + col);
    float a[4] = {v.x, v.y, v.z, v.w};
    float hs[4], ms[4];
#pragma unroll
    for (int k = 0; k < 4; k++) {
        __half h = __float2half_rn(a[k]);
        hs[k] = __half2float(h);
        ms[k] = a[k] - hs[k];
    }
    uint2 ph = make_uint2(packh2(hs[0], hs[1]), packh2(hs[2], hs[3]));
    uint2 pm = make_uint2(packh2(ms[0], ms[1]), packh2(ms[2], ms[3]));
    __half* d = W1p + (size_t)row * KB1 + col;
    *(uint2*)d         = ph;
    *(uint2*)(d + 768) = pm;
}

__global__ void split_w2_kernel(const float* __restrict__ w, __half* __restrict__ W2p)
{
    int i = blockIdx.x * blockDim.x + threadIdx.x;
    if (i >= N2 * 768) return;
    const int row = i / 768, col = (i % 768) * 4;
    float4 v = *(const float4*)(w + (size_t)row * 3072 + col);
    float a[4] = {v.x, v.y, v.z, v.w};
    float hs[4], ms[4];
#pragma unroll
    for (int k = 0; k < 4; k++) {
        __half h = __float2half_rn(a[k]);
        hs[k] = __half2float(h);
        ms[k] = a[k] - hs[k];
    }
    uint2 ph = make_uint2(packh2(hs[0], hs[1]), packh2(hs[2], hs[3]));
    uint2 pm = make_uint2(packh2(ms[0], ms[1]), packh2(ms[2], ms[3]));
    __half* d = W2p + (size_t)row * KB2 + col;
    *(uint2*)d          = ph;
    *(uint2*)(d + 3072) = pm;
}

// ---------------- LIF kernels ----------------
__global__ void lif1_kernel(const float* __restrict__ h, const float* __restrict__ b1,
                            __half* __restrict__ s1)
{
    int i = blockIdx.x * blockDim.x + threadIdx.x;
    if (i >= MR * (N1 / 4)) return;
    const int m = i / (N1 / 4), col = (i % (N1 / 4)) * 4;
    const float4 bb = *(const float4*)(b1 + col);
    float v[4] = {0.f, 0.f, 0.f, 0.f};
#pragma unroll
    for (int t = 0; t < 4; t++) {
        const size_t row = (size_t)(t * MR + m);
        float4 hv = *(const float4*)(h + row * N1 + col);
        float hh[4] = {hv.x + bb.x, hv.y + bb.y, hv.z + bb.z, hv.w + bb.w};
        float s[4];
#pragma unroll
        for (int k = 0; k < 4; k++) {
            v[k] = v[k] + (hh[k] - v[k]) * 0.5f;
            s[k] = (v[k] >= 1.0f) ? 1.0f : 0.0f;
            v[k] = v[k] * (1.0f - s[k]);
        }
        *(uint2*)(s1 + row * KA2 + col) =
            make_uint2(packh2(s[0], s[1]), packh2(s[2], s[3]));
    }
}

__global__ void lif2_kernel(const float* __restrict__ y, const float* __restrict__ b2,
                            float* __restrict__ out)
{
    int i = blockIdx.x * blockDim.x + threadIdx.x;
    if (i >= MR * (N2 / 4)) return;
    const int m = i / (N2 / 4), col = (i % (N2 / 4)) * 4;
    const float4 bb = *(const float4*)(b2 + col);
    float v[4] = {0.f, 0.f, 0.f, 0.f};
#pragma unroll
    for (int t = 0; t < 4; t++) {
        const size_t row = (size_t)(t * MR + m);
        float4 yv = *(const float4*)(y + row * N2 + col);
        float hh[4] = {yv.x + bb.x, yv.y + bb.y, yv.z + bb.z, yv.w + bb.w};
        float s[4];
#pragma unroll
        for (int k = 0; k < 4; k++) {
            v[k] = v[k] + (hh[k] - v[k]) * 0.5f;
            s[k] = (v[k] >= 1.0f) ? 1.0f : 0.0f;
            v[k] = v[k] * (1.0f - s[k]);
        }
        *(float4*)(out + row * N2 + col) = make_float4(s[0], s[1], s[2], s[3]);
    }
}

// ---------------- host ----------------
extern "C" void kernel_launch(void* const* d_in, const int* in_sizes, int n_in,
                              void* d_out, int out_size)
{
    const float* x  = (const float*)d_in[0];
    const float* W1 = (const float*)d_in[1];
    const float* b1 = (const float*)d_in[2];
    const float* W2 = (const float*)d_in[3];
    const float* b2 = (const float*)d_in[4];
    float* out = (float*)d_out;

    __half *A1, *W1p, *s1, *W2p;
    float *h, *y;
    cudaGetSymbolAddress((void**)&A1,  g_A1);
    cudaGetSymbolAddress((void**)&W1p, g_W1);
    cudaGetSymbolAddress((void**)&s1,  g_s1);
    cudaGetSymbolAddress((void**)&W2p, g_W2);
    cudaGetSymbolAddress((void**)&h,   g_h);
    cudaGetSymbolAddress((void**)&y,   g_y);

    const int SMEM = 3 * (int)STG_BYTES;   // 144KB
    cudaFuncSetAttribute(hgemm_kernel<1536, 768>,
                         cudaFuncAttributeMaxDynamicSharedMemorySize, SMEM);
    cudaFuncSetAttribute(hgemm_kernel<3072, (1 << 30)>,
                         cudaFuncAttributeMaxDynamicSharedMemorySize, SMEM);

    // splits
    split_x_kernel<<<(MT * 192 + 255) / 256, 256>>>(x, A1);
    split_w1_kernel<<<(N1 * 192 + 255) / 256, 256>>>(W1, W1p);
    split_w2_kernel<<<(N2 * 768 + 255) / 256, 256>>>(W2, W2p);

    // GEMM1: h = [xh|xm|xh] @ [w1h|w1h|w1m]^T   (M=25088, N=3072, Klog=2304)
    {
        dim3 grid(N1 / 128, MT / 256);   // (24, 98)
        hgemm_kernel<1536, 768><<<grid, 256, SMEM>>>(A1, W1p, h, 2304, N1, KA1, KB1);
    }
    // LIF1 -> s1
    lif1_kernel<<<(MR * (N1 / 4) + 255) / 256, 256>>>(h, b1, s1);
    // GEMM2: y = [s1|s1] @ [w2h|w2m]^T   (M=25088, N=768, Klog=6144)
    {
        dim3 grid(N2 / 128, MT / 256);   // (6, 98)
        hgemm_kernel<3072, (1 << 30)><<<grid, 256, SMEM>>>(s1, W2p, y, 6144, N2, KA2, KB2);
    }
    // LIF2 -> out
    lif2_kernel<<<(MR * (N2 / 4) + 255) / 256, 256>>>(y, b2, out);
}

// round 9
// speedup vs baseline: 1.1792x; 1.1792x over previous
#include <cuda_runtime.h>
#include <cuda_fp16.h>
#include <cstdint>

// ============================================================================
// SpikingMLP: fp16 split-product HMMA with LIF fused into GEMM epilogues.
//   GEMM1+LIF1: s1 = LIF([xh|xm|xh] @ [w1h|w1h|w1m]^T + b1)  -> fp16 binary
//   GEMM2+LIF2: out = LIF([s1|s1] @ [w2h|w2m]^T + b2)        -> fp32
// CTA tile: 32 m-rows x 4 timesteps (t interleaved into the 128 A rows) x 128 n.
//   row r in tile: t = (r>>3)&3, mloc = (r>>5)*8 + (r&7)
//   => each thread's 4 acc rows (mi,dpair) are the 4 t of ONE m: LIF in regs.
// GEMM core = round-5 config (best): BK=64, 2-stage cp.async, 8 warps 4mx2n,
// warp tile 32x64, ldmatrix + mma.sync m16n8k16, 2 CTAs/SM.
// ============================================================================

#define MT 25088      // T*B*N
#define MR 6272       // B*N
#define N1 3072
#define N2 768
#define KA1 1536      // phys A1 = [xh|xm]
#define KB1 1536      // phys W1 = [w1h|w1m]
#define KA2 3072      // phys s1
#define KB2 6144      // phys W2 = [w2h|w2m]

__device__ __align__(128) __half g_A1[(size_t)MT * KA1];
__device__ __align__(128) __half g_W1[(size_t)N1 * KB1];
__device__ __align__(128) __half g_s1[(size_t)MT * KA2];
__device__ __align__(128) __half g_W2[(size_t)N2 * KB2];

// ---------------- helpers ----------------
__device__ __forceinline__ uint32_t smem_u32(const void* p) {
    uint32_t a;
    asm("{ .reg .u64 t; cvta.to.shared.u64 t, %1; cvt.u32.u64 %0, t; }" : "=r"(a) : "l"(p));
    return a;
}
__device__ __forceinline__ void cp_async16(uint32_t dst, const void* src) {
    asm volatile("cp.async.cg.shared.global [%0], [%1], 16;" :: "r"(dst), "l"(src) : "memory");
}
__device__ __forceinline__ void cp_commit() { asm volatile("cp.async.commit_group;" ::: "memory"); }
__device__ __forceinline__ void cp_wait1()  { asm volatile("cp.async.wait_group 1;" ::: "memory"); }
__device__ __forceinline__ void cp_wait0()  { asm volatile("cp.async.wait_group 0;" ::: "memory"); }
__device__ __forceinline__ void ldmx4(uint32_t* r, uint32_t addr) {
    asm volatile("ldmatrix.sync.aligned.m8n8.x4.shared.b16 {%0,%1,%2,%3}, [%4];"
                 : "=r"(r[0]), "=r"(r[1]), "=r"(r[2]), "=r"(r[3]) : "r"(addr));
}
__device__ __forceinline__ void mma16816(float* d, const uint32_t* a, uint32_t b0, uint32_t b1) {
    asm volatile(
        "mma.sync.aligned.m16n8k16.row.col.f32.f16.f16.f32 "
        "{%0,%1,%2,%3}, {%4,%5,%6,%7}, {%8,%9}, {%0,%1,%2,%3};"
        : "+f"(d[0]), "+f"(d[1]), "+f"(d[2]), "+f"(d[3])
        : "r"(a[0]), "r"(a[1]), "r"(a[2]), "r"(a[3]), "r"(b0), "r"(b1));
}
__device__ __forceinline__ uint32_t packh2(float a, float b) {
    __half2 h = __floats2half2_rn(a, b);
    return *(uint32_t*)&h;
}

// ---------------- fused GEMM + LIF ----------------
// C_logical[Mrows=32x4t, N] = A[.,Klog] @ B[N,Klog]^T; LIF over t in epilogue.
// MODA/MODB: logical K col remap (k>=MOD ? k-MOD : k), stage(64)-aligned.
template<int MODA, int MODB, bool OUT_HALF>
__global__ __launch_bounds__(256, 2)
void gemm_lif(const __half* __restrict__ A, const __half* __restrict__ B,
              const float* __restrict__ bias, void* __restrict__ outp,
              int Klog, int N, int KaPhys, int KbPhys)
{
    extern __shared__ __align__(128) char smem_raw[];
    const uint32_t sbase = smem_u32(smem_raw);

    const int tid  = threadIdx.x;
    const int wid  = tid >> 5;
    const int lane = tid & 31;
    const int m0m  = blockIdx.y * 32;    // m block (32 m-values; 4 t each = 128 rows)
    const int n0   = blockIdx.x * 128;

    const int wm0 = (wid >> 1) * 32;     // warp row offset in 128-row tile
    const int wn0 = (wid & 1) * 64;

    const int lr = tid >> 3;             // loader row base (+j*32)
    const int lc = tid & 7;              // 16B chunk

    float acc[2][8][4];
#pragma unroll
    for (int mi = 0; mi < 2; mi++)
#pragma unroll
        for (int j = 0; j < 8; j++)
#pragma unroll
            for (int r = 0; r < 4; r++) acc[mi][j][r] = 0.0f;

    const int S = Klog >> 6;

#define LOAD_STAGE(sidx)                                                              \
    do {                                                                              \
        const int k0_  = (sidx) << 6;                                                 \
        const int ka0_ = (k0_ >= MODA) ? (k0_ - MODA) : k0_;                          \
        const int kb0_ = (k0_ >= MODB) ? (k0_ - MODB) : k0_;                          \
        const uint32_t Ad = sbase + (uint32_t)((sidx) & 1) * 32768u;                  \
        const uint32_t Bd = Ad + 16384u;                                              \
        _Pragma("unroll")                                                             \
        for (int j = 0; j < 4; j++) {                                                 \
            const int r_ = lr + j * 32;                                               \
            const uint32_t doff = (uint32_t)(r_ * 128 + ((lc ^ (r_ & 7)) << 4));      \
            const int t_  = (r_ >> 3) & 3;                                            \
            const int ml_ = ((r_ >> 5) << 3) + (r_ & 7);                              \
            cp_async16(Ad + doff,                                                     \
                (const char*)(A + (size_t)(t_ * MR + m0m + ml_) * KaPhys + ka0_) + lc * 16); \
            cp_async16(Bd + doff,                                                     \
                (const char*)(B + (size_t)(n0 + r_) * KbPhys + kb0_) + lc * 16);      \
        }                                                                             \
    } while (0)

    LOAD_STAGE(0);
    cp_commit();

    // ldmatrix per-thread geometry
    const int g  = lane >> 3;
    const int r8 = lane & 7;
    int a_m[2]; uint32_t a_rowoff[2];
#pragma unroll
    for (int mi = 0; mi < 2; mi++) {
        a_m[mi] = wm0 + mi * 16 + (g & 1) * 8 + r8;
        a_rowoff[mi] = (uint32_t)(a_m[mi] * 128);
    }
    int b_n[4]; uint32_t b_rowoff[4];
#pragma unroll
    for (int p = 0; p < 4; p++) {
        b_n[p] = wn0 + p * 16 + (g >> 1) * 8 + r8;
        b_rowoff[p] = (uint32_t)(b_n[p] * 128);
    }

    for (int s = 0; s < S; s++) {
        if (s + 1 < S) { LOAD_STAGE(s + 1); cp_commit(); cp_wait1(); }
        else           { cp_wait0(); }
        __syncthreads();

        const uint32_t Ab = sbase + (uint32_t)((s & 1) * 32768);
        const uint32_t Bb = Ab + 16384u;

#pragma unroll
        for (int ki = 0; ki < 4; ki++) {
            uint32_t af[2][4];
#pragma unroll
            for (int mi = 0; mi < 2; mi++) {
                const int c = 2 * ki + (g >> 1);
                ldmx4(af[mi], Ab + a_rowoff[mi] + (uint32_t)(((c ^ (a_m[mi] & 7)) << 4)));
            }
            uint32_t bf[4][4];
#pragma unroll
            for (int p = 0; p < 4; p++) {
                const int c = 2 * ki + (g & 1);
                ldmx4(bf[p], Bb + b_rowoff[p] + (uint32_t)(((c ^ (b_n[p] & 7)) << 4)));
            }
#pragma unroll
            for (int mi = 0; mi < 2; mi++)
#pragma unroll
                for (int p = 0; p < 4; p++) {
                    mma16816(acc[mi][2 * p],     af[mi], bf[p][0], bf[p][1]);
                    mma16816(acc[mi][2 * p + 1], af[mi], bf[p][2], bf[p][3]);
                }
        }
        __syncthreads();
    }

    // ---- epilogue: per-thread LIF over the 4 timesteps of one m value ----
    // thread's acc rows: wm0 + mi*16 + dp*8 + (lane>>2)
    //   -> t = 2*mi + dp ; m = m0m + (wid>>1)*8 + (lane>>2)   (wm0 multiple of 32)
    const int m = m0m + ((wid >> 1) << 3) + (lane >> 2);

#pragma unroll
    for (int j = 0; j < 8; j++) {
        const int col = n0 + wn0 + j * 8 + (lane & 3) * 2;
        const float bx = bias[col];
        const float by = bias[col + 1];
        float v0 = 0.f, v1 = 0.f;
#pragma unroll
        for (int t = 0; t < 4; t++) {
            const int mi = t >> 1, dp = t & 1;
            const float h0 = acc[mi][j][dp * 2 + 0] + bx;
            const float h1 = acc[mi][j][dp * 2 + 1] + by;
            v0 = v0 + (h0 - v0) * 0.5f;
            v1 = v1 + (h1 - v1) * 0.5f;
            const float s0 = (v0 >= 1.0f) ? 1.0f : 0.0f;
            const float s1v = (v1 >= 1.0f) ? 1.0f : 0.0f;
            const size_t idx = (size_t)(t * MR + m) * (size_t)N + (size_t)col;
            if (OUT_HALF) {
                *(uint32_t*)((__half*)outp + idx) = packh2(s0, s1v);
            } else {
                *(float2*)((float*)outp + idx) = make_float2(s0, s1v);
            }
            v0 *= (1.0f - s0);
            v1 *= (1.0f - s1v);
        }
    }
#undef LOAD_STAGE
}

// ---------------- split kernels ----------------
__global__ void split_x_kernel(const float* __restrict__ x, __half* __restrict__ A1)
{
    int i = blockIdx.x * blockDim.x + threadIdx.x;
    if (i >= MT * 192) return;
    const int row = i / 192, col = (i % 192) * 4;
    float4 v = *(const float4*)(x + (size_t)row * 768 + col);
    float a[4] = {v.x, v.y, v.z, v.w};
    float hs[4], ms[4];
#pragma unroll
    for (int k = 0; k < 4; k++) {
        __half h = __float2half_rn(a[k]);
        hs[k] = __half2float(h);
        ms[k] = a[k] - hs[k];
    }
    uint2 ph = make_uint2(packh2(hs[0], hs[1]), packh2(hs[2], hs[3]));
    uint2 pm = make_uint2(packh2(ms[0], ms[1]), packh2(ms[2], ms[3]));
    __half* d = A1 + (size_t)row * KA1 + col;
    *(uint2*)d         = ph;
    *(uint2*)(d + 768) = pm;
}

__global__ void split_w1_kernel(const float* __restrict__ w, __half* __restrict__ W1p)
{
    int i = blockIdx.x * blockDim.x + threadIdx.x;
    if (i >= N1 * 192) return;
    const int row = i / 192, col = (i % 192) * 4;
    float4 v = *(const float4*)(w + (size_t)row * 768 + col);
    float a[4] = {v.x, v.y, v.z, v.w};
    float hs[4], ms[4];
#pragma unroll
    for (int k = 0; k < 4; k++) {
        __half h = __float2half_rn(a[k]);
        hs[k] = __half2float(h);
        ms[k] = a[k] - hs[k];
    }
    uint2 ph = make_uint2(packh2(hs[0], hs[1]), packh2(hs[2], hs[3]));
    uint2 pm = make_uint2(packh2(ms[0], ms[1]), packh2(ms[2], ms[3]));
    __half* d = W1p + (size_t)row * KB1 + col;
    *(uint2*)d         = ph;
    *(uint2*)(d + 768) = pm;
}

__global__ void split_w2_kernel(const float* __restrict__ w, __half* __restrict__ W2p)
{
    int i = blockIdx.x * blockDim.x + threadIdx.x;
    if (i >= N2 * 768) return;
    const int row = i / 768, col = (i % 768) * 4;
    float4 v = *(const float4*)(w + (size_t)row * 3072 + col);
    float a[4] = {v.x, v.y, v.z, v.w};
    float hs[4], ms[4];
#pragma unroll
    for (int k = 0; k < 4; k++) {
        __half h = __float2half_rn(a[k]);
        hs[k] = __half2float(h);
        ms[k] = a[k] - hs[k];
    }
    uint2 ph = make_uint2(packh2(hs[0], hs[1]), packh2(hs[2], hs[3]));
    uint2 pm = make_uint2(packh2(ms[0], ms[1]), packh2(ms[2], ms[3]));
    __half* d = W2p + (size_t)row * KB2 + col;
    *(uint2*)d          = ph;
    *(uint2*)(d + 3072) = pm;
}

// ---------------- host ----------------
extern "C" void kernel_launch(void* const* d_in, const int* in_sizes, int n_in,
                              void* d_out, int out_size)
{
    const float* x  = (const float*)d_in[0];
    const float* W1 = (const float*)d_in[1];
    const float* b1 = (const float*)d_in[2];
    const float* W2 = (const float*)d_in[3];
    const float* b2 = (const float*)d_in[4];
    float* out = (float*)d_out;

    __half *A1, *W1p, *s1, *W2p;
    cudaGetSymbolAddress((void**)&A1,  g_A1);
    cudaGetSymbolAddress((void**)&W1p, g_W1);
    cudaGetSymbolAddress((void**)&s1,  g_s1);
    cudaGetSymbolAddress((void**)&W2p, g_W2);

    const int SMEM = 2 * 32768;   // 64KB: 2 stages x (16KB A + 16KB B)
    cudaFuncSetAttribute(gemm_lif<1536, 768, true>,
                         cudaFuncAttributeMaxDynamicSharedMemorySize, SMEM);
    cudaFuncSetAttribute(gemm_lif<3072, (1 << 30), false>,
                         cudaFuncAttributeMaxDynamicSharedMemorySize, SMEM);

    // splits
    split_x_kernel<<<(MT * 192 + 255) / 256, 256>>>(x, A1);
    split_w1_kernel<<<(N1 * 192 + 255) / 256, 256>>>(W1, W1p);
    split_w2_kernel<<<(N2 * 768 + 255) / 256, 256>>>(W2, W2p);

    // GEMM1 + LIF1 -> s1 (fp16 binary), Klog=2304
    {
        dim3 grid(N1 / 128, MR / 32);    // (24, 196)
        gemm_lif<1536, 768, true><<<grid, 256, SMEM>>>(
            A1, W1p, b1, (void*)s1, 2304, N1, KA1, KB1);
    }
    // GEMM2 + LIF2 -> out (fp32), Klog=6144
    {
        dim3 grid(N2 / 128, MR / 32);    // (6, 196)
        gemm_lif<3072, (1 << 30), false><<<grid, 256, SMEM>>>(
            s1, W2p, b2, (void*)out, 6144, N2, KA2, KB2);
    }
}